// round 1
// baseline (speedup 1.0000x reference)
#include <cuda_runtime.h>
#include <math.h>

// ---------------------------------------------------------------------------
// Scratch arena (worst case M1,M2 <= N = 2^20):
//   ps1(3M1) cnt1(M1) agg1(16M1) f1(32M1) ps2(3M2) cnt2(M2) agg2(64M2)
//   f2(128M2) agg3(128G)
// = 52*M1 + 196*M2 + 128*G floats <= 248*N + 131072
// ---------------------------------------------------------------------------
#define MAXN (1u << 20)
static __device__ float g_arena[248ull * MAXN + 131072ull + 64ull];

__device__ __forceinline__ float celu1(float x) { return x > 0.f ? x : expm1f(x); }

// ------------------------- segment mean (scatter) --------------------------
__global__ void k_scatter_mean(const float* __restrict__ p, const int* __restrict__ cl,
                               float* __restrict__ sum, float* __restrict__ cnt, int n) {
    int i = blockIdx.x * blockDim.x + threadIdx.x;
    if (i >= n) return;
    int c = cl[i];
    atomicAdd(&sum[3 * c + 0], p[3 * i + 0]);
    atomicAdd(&sum[3 * c + 1], p[3 * i + 1]);
    atomicAdd(&sum[3 * c + 2], p[3 * i + 2]);
    atomicAdd(&cnt[c], 1.0f);
}

__global__ void k_div3(float* __restrict__ ps, const float* __restrict__ cnt, int m) {
    int i = blockIdx.x * blockDim.x + threadIdx.x;
    if (i >= m) return;
    float inv = 1.0f / fmaxf(cnt[i], 1.0f);
    ps[3 * i + 0] *= inv;
    ps[3 * i + 1] *= inv;
    ps[3 * i + 2] *= inv;
}

// ------------------- stage 1 edge: [rgb,rel]@W1l -> relu -> segmax ----------
__global__ void k_edge1(const float* __restrict__ rgb, const float* __restrict__ pos,
                        const float* __restrict__ ps1, const int* __restrict__ cl,
                        const float* __restrict__ W, const float* __restrict__ b,
                        float* __restrict__ agg, int n) {
    __shared__ float Ws[64];
    __shared__ float bs[16];
    if (threadIdx.x < 64) Ws[threadIdx.x] = W[threadIdx.x];
    if (threadIdx.x < 16) bs[threadIdx.x] = b[threadIdx.x];
    __syncthreads();
    int i = blockIdx.x * blockDim.x + threadIdx.x;
    if (i >= n) return;
    int c = cl[i];
    float x0 = rgb[i];
    float rx = pos[3 * i + 0] - ps1[3 * c + 0];
    float ry = pos[3 * i + 1] - ps1[3 * c + 1];
    float rz = pos[3 * i + 2] - ps1[3 * c + 2];
    unsigned int* ag = (unsigned int*)(agg + 16 * c);
#pragma unroll
    for (int j = 0; j < 16; j++) {
        float m = bs[j];
        m = fmaf(x0, Ws[j], m);
        m = fmaf(rx, Ws[16 + j], m);
        m = fmaf(ry, Ws[32 + j], m);
        m = fmaf(rz, Ws[48 + j], m);
        m = fmaxf(m, 0.0f);
        atomicMax(ag + j, __float_as_uint(m));
    }
}

// ------------------------- f1 = celu(agg1 @ W1g + b) ------------------------
__global__ void k_f1(const float* __restrict__ agg, const float* __restrict__ W,
                     const float* __restrict__ b, float* __restrict__ f1, int m1) {
    __shared__ float Ws[512];
    __shared__ float bs[32];
    for (int t = threadIdx.x; t < 512; t += blockDim.x) Ws[t] = W[t];
    if (threadIdx.x < 32) bs[threadIdx.x] = b[threadIdx.x];
    __syncthreads();
    int idx = blockIdx.x * blockDim.x + threadIdx.x;
    if (idx >= m1 * 32) return;
    int m = idx >> 5, j = idx & 31;
    const float* a = agg + 16 * m;
    float acc = bs[j];
#pragma unroll
    for (int k = 0; k < 16; k++) acc = fmaf(__ldg(a + k), Ws[k * 32 + j], acc);
    f1[idx] = celu1(acc);
}

// ---- stage 2 edge: [f1,rel](35) @ W2l(35x64) -> relu -> segmax into agg2 ----
// 128 threads = 2 groups x 64 outputs; each group handles 4 edges per batch.
__global__ void k_edge2(const float* __restrict__ f1, const float* __restrict__ ps1,
                        const float* __restrict__ ps2, const int* __restrict__ cl2,
                        const float* __restrict__ W, const float* __restrict__ b,
                        float* __restrict__ agg, int n) {
    __shared__ float Wsh[36 * 64];
    __shared__ float bsh[64];
    __shared__ float ins[8 * 36];
    __shared__ int cidx[8];
    int tid = threadIdx.x;
    for (int t = tid; t < 36 * 64; t += 128) Wsh[t] = (t < 35 * 64) ? W[t] : 0.0f;
    if (tid < 64) bsh[tid] = b[tid];
    int g = tid >> 6, j = tid & 63;
    for (int base = blockIdx.x * 8; base < n; base += gridDim.x * 8) {
        __syncthreads();
        for (int s = tid; s < 8 * 36; s += 128) {
            int e = s / 36, k = s - 36 * e;
            int i = base + e;
            float v = 0.0f;
            if (i < n) {
                if (k < 32) v = f1[i * 32 + k];
                else if (k < 35) {
                    int c = cl2[i];
                    v = ps1[3 * i + (k - 32)] - ps2[3 * c + (k - 32)];
                }
            }
            ins[s] = v;
        }
        if (tid < 8) cidx[tid] = (base + tid < n) ? cl2[base + tid] : -1;
        __syncthreads();
        float a0 = bsh[j], a1 = a0, a2 = a0, a3 = a0;
        const float* I = &ins[g * 4 * 36];
#pragma unroll
        for (int k4 = 0; k4 < 36; k4 += 4) {
            float w0 = Wsh[(k4 + 0) * 64 + j];
            float w1 = Wsh[(k4 + 1) * 64 + j];
            float w2 = Wsh[(k4 + 2) * 64 + j];
            float w3 = Wsh[(k4 + 3) * 64 + j];
            float4 x0 = *(const float4*)(I + 0 * 36 + k4);
            float4 x1 = *(const float4*)(I + 1 * 36 + k4);
            float4 x2 = *(const float4*)(I + 2 * 36 + k4);
            float4 x3 = *(const float4*)(I + 3 * 36 + k4);
            a0 = fmaf(x0.x, w0, a0); a0 = fmaf(x0.y, w1, a0); a0 = fmaf(x0.z, w2, a0); a0 = fmaf(x0.w, w3, a0);
            a1 = fmaf(x1.x, w0, a1); a1 = fmaf(x1.y, w1, a1); a1 = fmaf(x1.z, w2, a1); a1 = fmaf(x1.w, w3, a1);
            a2 = fmaf(x2.x, w0, a2); a2 = fmaf(x2.y, w1, a2); a2 = fmaf(x2.z, w2, a2); a2 = fmaf(x2.w, w3, a2);
            a3 = fmaf(x3.x, w0, a3); a3 = fmaf(x3.y, w1, a3); a3 = fmaf(x3.z, w2, a3); a3 = fmaf(x3.w, w3, a3);
        }
        int c0 = cidx[g * 4 + 0], c1 = cidx[g * 4 + 1], c2 = cidx[g * 4 + 2], c3 = cidx[g * 4 + 3];
        if (c0 >= 0) atomicMax((unsigned int*)&agg[c0 * 64 + j], __float_as_uint(fmaxf(a0, 0.0f)));
        if (c1 >= 0) atomicMax((unsigned int*)&agg[c1 * 64 + j], __float_as_uint(fmaxf(a1, 0.0f)));
        if (c2 >= 0) atomicMax((unsigned int*)&agg[c2 * 64 + j], __float_as_uint(fmaxf(a2, 0.0f)));
        if (c3 >= 0) atomicMax((unsigned int*)&agg[c3 * 64 + j], __float_as_uint(fmaxf(a3, 0.0f)));
    }
}

// -------------------- f2 = celu(agg2(64) @ W2g(64x128) + b) -----------------
__global__ void k_f2(const float* __restrict__ agg, const float* __restrict__ W,
                     const float* __restrict__ b, float* __restrict__ f2, int m) {
    __shared__ float Wsh[64 * 128];
    __shared__ float bsh[128];
    __shared__ float ins[4 * 64];
    int tid = threadIdx.x;  // 128
    for (int t = tid; t < 64 * 128; t += 128) Wsh[t] = W[t];
    bsh[tid] = b[tid];
    for (int base = blockIdx.x * 4; base < m; base += gridDim.x * 4) {
        __syncthreads();
        for (int s = tid; s < 256; s += 128) {
            int e = s >> 6, k = s & 63;
            int i = base + e;
            ins[s] = (i < m) ? agg[i * 64 + k] : 0.0f;
        }
        __syncthreads();
        float a0 = bsh[tid], a1 = a0, a2 = a0, a3 = a0;
#pragma unroll
        for (int k4 = 0; k4 < 64; k4 += 4) {
            float w0 = Wsh[(k4 + 0) * 128 + tid];
            float w1 = Wsh[(k4 + 1) * 128 + tid];
            float w2 = Wsh[(k4 + 2) * 128 + tid];
            float w3 = Wsh[(k4 + 3) * 128 + tid];
            float4 x0 = *(const float4*)&ins[0 * 64 + k4];
            float4 x1 = *(const float4*)&ins[1 * 64 + k4];
            float4 x2 = *(const float4*)&ins[2 * 64 + k4];
            float4 x3 = *(const float4*)&ins[3 * 64 + k4];
            a0 = fmaf(x0.x, w0, a0); a0 = fmaf(x0.y, w1, a0); a0 = fmaf(x0.z, w2, a0); a0 = fmaf(x0.w, w3, a0);
            a1 = fmaf(x1.x, w0, a1); a1 = fmaf(x1.y, w1, a1); a1 = fmaf(x1.z, w2, a1); a1 = fmaf(x1.w, w3, a1);
            a2 = fmaf(x2.x, w0, a2); a2 = fmaf(x2.y, w1, a2); a2 = fmaf(x2.z, w2, a2); a2 = fmaf(x2.w, w3, a2);
            a3 = fmaf(x3.x, w0, a3); a3 = fmaf(x3.y, w1, a3); a3 = fmaf(x3.z, w2, a3); a3 = fmaf(x3.w, w3, a3);
        }
        if (base + 0 < m) f2[(base + 0) * 128 + tid] = celu1(a0);
        if (base + 1 < m) f2[(base + 1) * 128 + tid] = celu1(a1);
        if (base + 2 < m) f2[(base + 2) * 128 + tid] = celu1(a2);
        if (base + 3 < m) f2[(base + 3) * 128 + tid] = celu1(a3);
    }
}

// ---- stage 3 edge: [f2,ps2](131) @ W3l(131x128) -> relu -> segmax (G segs) --
// dynamic smem: W(132*128) + b(128) + ins(4*132) + cidx(4)
#define SMEM3_FLOATS (132 * 128 + 128 + 4 * 132 + 4)
__global__ void k_edge3(const float* __restrict__ f2, const float* __restrict__ ps2,
                        const int* __restrict__ b2, const float* __restrict__ W,
                        const float* __restrict__ bias, float* __restrict__ agg, int n) {
    extern __shared__ float sm[];
    float* Wsh = sm;                 // 132*128
    float* bsh = Wsh + 132 * 128;    // 128
    float* ins = bsh + 128;          // 4*132  (16B-aligned: offset 17024 floats)
    int* cidx = (int*)(ins + 4 * 132);
    int tid = threadIdx.x;  // 128
    for (int t = tid; t < 132 * 128; t += 128) Wsh[t] = (t < 131 * 128) ? W[t] : 0.0f;
    bsh[tid] = bias[tid];
    for (int base = blockIdx.x * 4; base < n; base += gridDim.x * 4) {
        __syncthreads();
        for (int s = tid; s < 4 * 132; s += 128) {
            int e = s / 132, k = s - 132 * e;
            int i = base + e;
            float v = 0.0f;
            if (i < n) {
                if (k < 128) v = f2[i * 128 + k];
                else if (k < 131) v = ps2[3 * i + (k - 128)];
            }
            ins[s] = v;
        }
        if (tid < 4) cidx[tid] = (base + tid < n) ? b2[base + tid] : -1;
        __syncthreads();
        float a0 = bsh[tid], a1 = a0, a2 = a0, a3 = a0;
#pragma unroll
        for (int k4 = 0; k4 < 132; k4 += 4) {
            float w0 = Wsh[(k4 + 0) * 128 + tid];
            float w1 = Wsh[(k4 + 1) * 128 + tid];
            float w2 = Wsh[(k4 + 2) * 128 + tid];
            float w3 = Wsh[(k4 + 3) * 128 + tid];
            float4 x0 = *(const float4*)&ins[0 * 132 + k4];
            float4 x1 = *(const float4*)&ins[1 * 132 + k4];
            float4 x2 = *(const float4*)&ins[2 * 132 + k4];
            float4 x3 = *(const float4*)&ins[3 * 132 + k4];
            a0 = fmaf(x0.x, w0, a0); a0 = fmaf(x0.y, w1, a0); a0 = fmaf(x0.z, w2, a0); a0 = fmaf(x0.w, w3, a0);
            a1 = fmaf(x1.x, w0, a1); a1 = fmaf(x1.y, w1, a1); a1 = fmaf(x1.z, w2, a1); a1 = fmaf(x1.w, w3, a1);
            a2 = fmaf(x2.x, w0, a2); a2 = fmaf(x2.y, w1, a2); a2 = fmaf(x2.z, w2, a2); a2 = fmaf(x2.w, w3, a2);
            a3 = fmaf(x3.x, w0, a3); a3 = fmaf(x3.y, w1, a3); a3 = fmaf(x3.z, w2, a3); a3 = fmaf(x3.w, w3, a3);
        }
        int c0 = cidx[0], c1 = cidx[1], c2 = cidx[2], c3 = cidx[3];
        if (c0 >= 0) atomicMax((unsigned int*)&agg[c0 * 128 + tid], __float_as_uint(fmaxf(a0, 0.0f)));
        if (c1 >= 0) atomicMax((unsigned int*)&agg[c1 * 128 + tid], __float_as_uint(fmaxf(a1, 0.0f)));
        if (c2 >= 0) atomicMax((unsigned int*)&agg[c2 * 128 + tid], __float_as_uint(fmaxf(a2, 0.0f)));
        if (c3 >= 0) atomicMax((unsigned int*)&agg[c3 * 128 + tid], __float_as_uint(fmaxf(a3, 0.0f)));
    }
}

// -------------------- f3 = celu(agg3(128) @ W3g(128x256) + b) ---------------
__global__ void k_f3(const float* __restrict__ agg3, const float* __restrict__ W,
                     const float* __restrict__ b, float* __restrict__ f3, int G) {
    int idx = blockIdx.x * blockDim.x + threadIdx.x;
    if (idx >= G * 256) return;
    int g = idx >> 8, j = idx & 255;
    const float* a = agg3 + g * 128;
    float acc = __ldg(b + j);
#pragma unroll 8
    for (int k = 0; k < 128; k++) acc = fmaf(__ldg(a + k), __ldg(W + k * 256 + j), acc);
    f3[idx] = celu1(acc);
}

// ------- head: out = f3 @ Wlin + blin; mu/sigma/z -> write all outputs -------
__global__ void k_head(const float* __restrict__ f3, const float* __restrict__ W,
                       const float* __restrict__ b, const float* __restrict__ eps,
                       float* __restrict__ out, int G) {
    __shared__ float row[256];
    int g = blockIdx.x;
    int j = threadIdx.x;  // 128
    for (int t = j; t < 256; t += 128) row[t] = f3[g * 256 + t];
    __syncthreads();
    float mu = __ldg(b + j), s = __ldg(b + j + 128);
#pragma unroll 4
    for (int k = 0; k < 256; k++) {
        float x = row[k];
        mu = fmaf(x, __ldg(W + k * 256 + j), mu);
        s = fmaf(x, __ldg(W + k * 256 + j + 128), s);
    }
    float sig = fmaxf(s, 0.0f) + log1pf(expf(-fabsf(s)));
    float z = fmaf(sig, eps[g * 128 + j], mu);
    // layout: z_what[G,64] | z_mask[G,64] | mu[G,128] | sigma[G,128] | f3[G,256]
    out[(size_t)G * 128 + g * 128 + j] = mu;
    out[(size_t)G * 256 + g * 128 + j] = sig;
    if (j < 64) out[g * 64 + j] = z;
    else out[(size_t)G * 64 + g * 64 + (j - 64)] = z;
}

// ---------------------------------------------------------------------------
extern "C" void kernel_launch(void* const* d_in, const int* in_sizes, int n_in,
                              void* d_out, int out_size) {
    const float* rgb = (const float*)d_in[0];
    const float* pos = (const float*)d_in[1];
    const float* W1l = (const float*)d_in[3];
    const float* b1l = (const float*)d_in[4];
    const float* W1g = (const float*)d_in[5];
    const float* b1g = (const float*)d_in[6];
    const float* W2l = (const float*)d_in[7];
    const float* b2l = (const float*)d_in[8];
    const float* W2g = (const float*)d_in[9];
    const float* b2g = (const float*)d_in[10];
    const float* W3l = (const float*)d_in[11];
    const float* b3l = (const float*)d_in[12];
    const float* W3g = (const float*)d_in[13];
    const float* b3g = (const float*)d_in[14];
    const float* Wlin = (const float*)d_in[15];
    const float* blin = (const float*)d_in[16];
    const float* eps = (const float*)d_in[17];
    const int* cl1 = (const int*)d_in[19];
    const int* cl2 = (const int*)d_in[20];
    const int* bt2 = (const int*)d_in[21];

    int N = in_sizes[0];        // rgb is [N,1]
    int G = in_sizes[2] / 3;    // glimpse_center is [G,3]
    int M1 = in_sizes[20];      // cluster2 has M1 entries
    int M2 = in_sizes[21];      // batch2 has M2 entries

    float* A = nullptr;
    cudaGetSymbolAddress((void**)&A, g_arena);
    size_t o = 0;
    float* ps1 = A + o;  o += 3ull * M1;
    float* cnt1 = A + o; o += (size_t)M1;
    float* agg1 = A + o; o += 16ull * M1;
    float* f1 = A + o;   o += 32ull * M1;
    float* ps2 = A + o;  o += 3ull * M2;
    float* cnt2 = A + o; o += (size_t)M2;
    float* agg2 = A + o; o += 64ull * M2;
    float* f2 = A + o;   o += 128ull * M2;
    float* agg3 = A + o; o += 128ull * G;

    float* out = (float*)d_out;
    float* f3 = out + (size_t)G * 384;

    // zero ps1+cnt1+agg1 (contiguous: 20*M1 floats), ps2+cnt2+agg2 (68*M2), agg3
    cudaMemsetAsync(ps1, 0, 20ull * M1 * sizeof(float), 0);
    cudaMemsetAsync(ps2, 0, 68ull * M2 * sizeof(float), 0);
    cudaMemsetAsync(agg3, 0, 128ull * G * sizeof(float), 0);

    k_scatter_mean<<<(N + 255) / 256, 256>>>(pos, cl1, ps1, cnt1, N);
    k_div3<<<(M1 + 255) / 256, 256>>>(ps1, cnt1, M1);
    k_edge1<<<(N + 255) / 256, 256>>>(rgb, pos, ps1, cl1, W1l, b1l, agg1, N);
    k_f1<<<((size_t)M1 * 32 + 255) / 256, 256>>>(agg1, W1g, b1g, f1, M1);

    k_scatter_mean<<<(M1 + 255) / 256, 256>>>(ps1, cl2, ps2, cnt2, M1);
    k_div3<<<(M2 + 255) / 256, 256>>>(ps2, cnt2, M2);
    k_edge2<<<1184, 128>>>(f1, ps1, ps2, cl2, W2l, b2l, agg2, M1);
    k_f2<<<888, 128>>>(agg2, W2g, b2g, f2, M2);

    cudaFuncSetAttribute(k_edge3, cudaFuncAttributeMaxDynamicSharedMemorySize,
                         SMEM3_FLOATS * sizeof(float));
    k_edge3<<<444, 128, SMEM3_FLOATS * sizeof(float)>>>(f2, ps2, bt2, W3l, b3l, agg3, M2);

    k_f3<<<(G * 256 + 255) / 256, 256>>>(agg3, W3g, b3g, f3, G);
    k_head<<<G, 128>>>(f3, Wlin, blin, eps, out, G);
}

// round 2
// speedup vs baseline: 1.3322x; 1.3322x over previous
#include <cuda_runtime.h>
#include <math.h>

// ---------------------------------------------------------------------------
// Scratch arena:
//   ps1(3M1) cnt1(M1) agg1(16M1) | ps2(3M2) cnt2(M2) agg2(64M2) | agg3(128G)
//   + packed weights (27904 floats)
// ---------------------------------------------------------------------------
#define MAXN (1u << 20)
static __device__ float g_arena[88ull * MAXN + 262144ull];

__device__ __forceinline__ float celu1(float x) { return x > 0.f ? x : expm1f(x); }

// ---- packed f32x2 helpers ----
__device__ __forceinline__ void ffma2(unsigned long long& d, unsigned long long a,
                                      unsigned long long b) {
    asm("fma.rn.f32x2 %0, %1, %2, %0;" : "+l"(d) : "l"(a), "l"(b));
}
__device__ __forceinline__ float ull_sum(unsigned long long v) {
    float a, b;
    asm("mov.b64 {%0, %1}, %2;" : "=f"(a), "=f"(b) : "l"(v));
    return a + b;
}
__device__ __forceinline__ unsigned long long ld2(const float* p) {
    return *(const unsigned long long*)p;
}

// ------------------- weight pre-pack: k-paired interleave -------------------
// Wp[k2*(2C) + 2j + s] = W[(2*k2+s)*C + j], zero-padded beyond K.
__device__ __forceinline__ void packw(float* dst, const float* src, int K, int C, int t) {
    int k2 = t / (2 * C);
    int col = t - k2 * 2 * C;
    int j = col >> 1;
    int k = 2 * k2 + (col & 1);
    dst[t] = (k < K) ? src[k * C + j] : 0.0f;
}
// sizes: Wp1g 8*64=512, Wp2l 18*128=2304, Wp2g 32*256=8192, Wp3l 66*256=16896
__global__ void k_prep(const float* __restrict__ W1g, const float* __restrict__ W2l,
                       const float* __restrict__ W2g, const float* __restrict__ W3l,
                       float* Wp1g, float* Wp2l, float* Wp2g, float* Wp3l) {
    int idx = blockIdx.x * blockDim.x + threadIdx.x;
    if (idx < 512) packw(Wp1g, W1g, 16, 32, idx);
    else if (idx < 512 + 2304) packw(Wp2l, W2l, 35, 64, idx - 512);
    else if (idx < 512 + 2304 + 8192) packw(Wp2g, W2g, 64, 128, idx - 512 - 2304);
    else if (idx < 512 + 2304 + 8192 + 16896) packw(Wp3l, W3l, 131, 128, idx - 512 - 2304 - 8192);
}

// ------------------------- segment mean (scatter) --------------------------
__global__ void k_scatter_mean(const float* __restrict__ p, const int* __restrict__ cl,
                               float* __restrict__ sum, float* __restrict__ cnt, int n) {
    int i = blockIdx.x * blockDim.x + threadIdx.x;
    if (i >= n) return;
    int c = cl[i];
    atomicAdd(&sum[3 * c + 0], p[3 * i + 0]);
    atomicAdd(&sum[3 * c + 1], p[3 * i + 1]);
    atomicAdd(&sum[3 * c + 2], p[3 * i + 2]);
    atomicAdd(&cnt[c], 1.0f);
}

__global__ void k_div3(float* __restrict__ ps, const float* __restrict__ cnt, int m) {
    int i = blockIdx.x * blockDim.x + threadIdx.x;
    if (i >= m) return;
    float inv = 1.0f / fmaxf(cnt[i], 1.0f);
    ps[3 * i + 0] *= inv;
    ps[3 * i + 1] *= inv;
    ps[3 * i + 2] *= inv;
}

// ------------------- stage 1 edge: [rgb,rel]@W1l -> relu -> segmax ----------
__global__ void k_edge1(const float* __restrict__ rgb, const float* __restrict__ pos,
                        const float* __restrict__ ps1, const int* __restrict__ cl,
                        const float* __restrict__ W, const float* __restrict__ b,
                        float* __restrict__ agg, int n) {
    __shared__ float Ws[64];
    __shared__ float bs[16];
    if (threadIdx.x < 64) Ws[threadIdx.x] = W[threadIdx.x];
    if (threadIdx.x < 16) bs[threadIdx.x] = b[threadIdx.x];
    __syncthreads();
    int i = blockIdx.x * blockDim.x + threadIdx.x;
    if (i >= n) return;
    int c = cl[i];
    float x0 = rgb[i];
    float rx = pos[3 * i + 0] - ps1[3 * c + 0];
    float ry = pos[3 * i + 1] - ps1[3 * c + 1];
    float rz = pos[3 * i + 2] - ps1[3 * c + 2];
    unsigned int* ag = (unsigned int*)(agg + 16 * c);
#pragma unroll
    for (int j = 0; j < 16; j++) {
        float m = bs[j];
        m = fmaf(x0, Ws[j], m);
        m = fmaf(rx, Ws[16 + j], m);
        m = fmaf(ry, Ws[32 + j], m);
        m = fmaf(rz, Ws[48 + j], m);
        m = fmaxf(m, 0.0f);
        atomicMax(ag + j, __float_as_uint(m));
    }
}

// ---------------------------------------------------------------------------
// Fused stage-2: per edge i (level-1 voxel):
//   f1_i = celu(agg1_i @ W1g + b1g)            (16 -> 32)
//   msg  = relu([f1_i, ps1_i - ps2_c] @ W2l + b2l)   (35 -> 64)
//   agg2[c] = max(agg2[c], msg)
// 256 threads, E=16 edges per iteration.
// ---------------------------------------------------------------------------
__global__ void k_edge2f(const float* __restrict__ agg1, const float* __restrict__ ps1,
                         const float* __restrict__ ps2, const int* __restrict__ cl2,
                         const float* __restrict__ Wp1g, const float* __restrict__ b1g,
                         const float* __restrict__ Wp2l, const float* __restrict__ b2l,
                         float* __restrict__ agg2, int n) {
    __shared__ __align__(16) float Wl[18 * 128];
    __shared__ __align__(16) float Wg[8 * 64];
    __shared__ __align__(16) float ins[16 * 36];
    __shared__ __align__(16) float a1[16 * 16];
    __shared__ float bg[32];
    __shared__ float bl[64];
    __shared__ int cidx[16];
    int tid = threadIdx.x;
    for (int t = tid; t < 18 * 128; t += 256) Wl[t] = Wp2l[t];
    for (int t = tid; t < 8 * 64; t += 256) Wg[t] = Wp1g[t];
    if (tid < 32) bg[tid] = b1g[tid];
    if (tid < 64) bl[tid] = b2l[tid];
    for (int base = blockIdx.x * 16; base < n; base += gridDim.x * 16) {
        __syncthreads();
        if (tid < 64) {
            int e = tid >> 2, q = tid & 3;
            int i = base + e;
            float4 v = make_float4(0.f, 0.f, 0.f, 0.f);
            if (i < n) v = *(const float4*)(agg1 + (size_t)i * 16 + 4 * q);
            *(float4*)&a1[e * 16 + 4 * q] = v;
        } else if (tid < 80) {
            int e = tid - 64;
            int i = base + e;
            int c = -1;
            float rx = 0.f, ry = 0.f, rz = 0.f;
            if (i < n) {
                c = cl2[i];
                rx = ps1[3 * i + 0] - ps2[3 * c + 0];
                ry = ps1[3 * i + 1] - ps2[3 * c + 1];
                rz = ps1[3 * i + 2] - ps2[3 * c + 2];
            }
            cidx[e] = c;
            ins[e * 36 + 32] = rx;
            ins[e * 36 + 33] = ry;
            ins[e * 36 + 34] = rz;
            ins[e * 36 + 35] = 0.f;
        }
        __syncthreads();
        // f1: 16 edges x 32 cols; thread -> (j = tid&31, rows e0,e0+1)
        {
            int j = tid & 31;
            int e0 = (tid >> 5) * 2;
            unsigned long long acc0 = 0ull, acc1 = 0ull;
#pragma unroll
            for (int k2 = 0; k2 < 8; k2++) {
                unsigned long long w = ld2(&Wg[k2 * 64 + 2 * j]);
                ffma2(acc0, ld2(&a1[e0 * 16 + 2 * k2]), w);
                ffma2(acc1, ld2(&a1[(e0 + 1) * 16 + 2 * k2]), w);
            }
            float bb = bg[j];
            ins[e0 * 36 + j] = celu1(ull_sum(acc0) + bb);
            ins[(e0 + 1) * 36 + j] = celu1(ull_sum(acc1) + bb);
        }
        __syncthreads();
        // GEMM 36->64 for 16 edges: 4 groups x 64 j, 4 edges each
        {
            int g = tid >> 6, j = tid & 63;
            const float* I = &ins[g * 4 * 36];
            unsigned long long acc0 = 0ull, acc1 = 0ull, acc2 = 0ull, acc3 = 0ull;
#pragma unroll
            for (int k2 = 0; k2 < 18; k2++) {
                unsigned long long w = ld2(&Wl[k2 * 128 + 2 * j]);
                ffma2(acc0, ld2(&I[0 * 36 + 2 * k2]), w);
                ffma2(acc1, ld2(&I[1 * 36 + 2 * k2]), w);
                ffma2(acc2, ld2(&I[2 * 36 + 2 * k2]), w);
                ffma2(acc3, ld2(&I[3 * 36 + 2 * k2]), w);
            }
            float bb = bl[j];
            float r[4];
            int c[4];
            r[0] = fmaxf(ull_sum(acc0) + bb, 0.f);
            r[1] = fmaxf(ull_sum(acc1) + bb, 0.f);
            r[2] = fmaxf(ull_sum(acc2) + bb, 0.f);
            r[3] = fmaxf(ull_sum(acc3) + bb, 0.f);
            c[0] = cidx[g * 4 + 0];
            c[1] = cidx[g * 4 + 1];
            c[2] = cidx[g * 4 + 2];
            c[3] = cidx[g * 4 + 3];
#pragma unroll
            for (int e = 0; e < 4; e++) {
                if (c[e] < 0) continue;
#pragma unroll
                for (int f = e + 1; f < 4; f++)
                    if (c[f] == c[e]) { r[e] = fmaxf(r[e], r[f]); c[f] = -1; }
                atomicMax((unsigned int*)&agg2[(size_t)c[e] * 64 + j], __float_as_uint(r[e]));
            }
        }
    }
}

// ---------------------------------------------------------------------------
// Fused stage-3: per edge i (level-2 voxel):
//   f2_i = celu(agg2_i @ W2g + b2g)           (64 -> 128)
//   msg  = relu([f2_i, ps2_i] @ W3l + b3l)    (131 -> 128)
//   agg3[batch2_i] = max(..., msg)
// 256 threads, E=8 edges per iteration; dynamic smem.
// ---------------------------------------------------------------------------
#define SM3 (16896 + 8192 + 8 * 132 + 8 * 64 + 128 + 128 + 8)
__global__ void k_edge3f(const float* __restrict__ agg2, const float* __restrict__ ps2,
                         const int* __restrict__ bt2,
                         const float* __restrict__ Wp2g, const float* __restrict__ b2g,
                         const float* __restrict__ Wp3l, const float* __restrict__ b3l,
                         float* __restrict__ agg3, int n) {
    extern __shared__ float sm[];
    float* Wl = sm;                  // 66*256
    float* Wg = Wl + 16896;          // 32*256
    float* ins = Wg + 8192;          // 8*132
    float* a2 = ins + 8 * 132;       // 8*64
    float* bgs = a2 + 8 * 64;        // 128
    float* bls = bgs + 128;          // 128
    int* cidx = (int*)(bls + 128);   // 8
    int tid = threadIdx.x;
    for (int t = tid; t < 16896; t += 256) Wl[t] = Wp3l[t];
    for (int t = tid; t < 8192; t += 256) Wg[t] = Wp2g[t];
    if (tid < 128) {
        bgs[tid] = b2g[tid];
        bls[tid] = b3l[tid];
    }
    for (int base = blockIdx.x * 8; base < n; base += gridDim.x * 8) {
        __syncthreads();
        if (tid < 128) {
            int e = tid >> 4, q = tid & 15;
            int i = base + e;
            float4 v = make_float4(0.f, 0.f, 0.f, 0.f);
            if (i < n) v = *(const float4*)(agg2 + (size_t)i * 64 + 4 * q);
            *(float4*)&a2[e * 64 + 4 * q] = v;
        } else if (tid < 136) {
            int e = tid - 128;
            int i = base + e;
            int c = -1;
            float x = 0.f, y = 0.f, z = 0.f;
            if (i < n) {
                c = bt2[i];
                x = ps2[3 * i + 0];
                y = ps2[3 * i + 1];
                z = ps2[3 * i + 2];
            }
            cidx[e] = c;
            ins[e * 132 + 128] = x;
            ins[e * 132 + 129] = y;
            ins[e * 132 + 130] = z;
            ins[e * 132 + 131] = 0.f;
        }
        __syncthreads();
        // f2: 8 edges x 128 cols; thread -> (j, 4 rows), w shared across rows
        {
            int g = tid >> 7, j = tid & 127;
            int e0 = g * 4;
            unsigned long long acc0 = 0ull, acc1 = 0ull, acc2 = 0ull, acc3 = 0ull;
#pragma unroll
            for (int k2 = 0; k2 < 32; k2++) {
                unsigned long long w = ld2(&Wg[k2 * 256 + 2 * j]);
                ffma2(acc0, ld2(&a2[(e0 + 0) * 64 + 2 * k2]), w);
                ffma2(acc1, ld2(&a2[(e0 + 1) * 64 + 2 * k2]), w);
                ffma2(acc2, ld2(&a2[(e0 + 2) * 64 + 2 * k2]), w);
                ffma2(acc3, ld2(&a2[(e0 + 3) * 64 + 2 * k2]), w);
            }
            float bb = bgs[j];
            ins[(e0 + 0) * 132 + j] = celu1(ull_sum(acc0) + bb);
            ins[(e0 + 1) * 132 + j] = celu1(ull_sum(acc1) + bb);
            ins[(e0 + 2) * 132 + j] = celu1(ull_sum(acc2) + bb);
            ins[(e0 + 3) * 132 + j] = celu1(ull_sum(acc3) + bb);
        }
        __syncthreads();
        // GEMM 132->128 for 8 edges: 2 groups x 128 j, 4 edges each
        {
            int g = tid >> 7, j = tid & 127;
            const float* I = &ins[g * 4 * 132];
            unsigned long long acc0 = 0ull, acc1 = 0ull, acc2 = 0ull, acc3 = 0ull;
#pragma unroll 6
            for (int k2 = 0; k2 < 66; k2++) {
                unsigned long long w = ld2(&Wl[k2 * 256 + 2 * j]);
                ffma2(acc0, ld2(&I[0 * 132 + 2 * k2]), w);
                ffma2(acc1, ld2(&I[1 * 132 + 2 * k2]), w);
                ffma2(acc2, ld2(&I[2 * 132 + 2 * k2]), w);
                ffma2(acc3, ld2(&I[3 * 132 + 2 * k2]), w);
            }
            float bb = bls[j];
            float r[4];
            int c[4];
            r[0] = fmaxf(ull_sum(acc0) + bb, 0.f);
            r[1] = fmaxf(ull_sum(acc1) + bb, 0.f);
            r[2] = fmaxf(ull_sum(acc2) + bb, 0.f);
            r[3] = fmaxf(ull_sum(acc3) + bb, 0.f);
            c[0] = cidx[g * 4 + 0];
            c[1] = cidx[g * 4 + 1];
            c[2] = cidx[g * 4 + 2];
            c[3] = cidx[g * 4 + 3];
#pragma unroll
            for (int e = 0; e < 4; e++) {
                if (c[e] < 0) continue;
#pragma unroll
                for (int f = e + 1; f < 4; f++)
                    if (c[f] == c[e]) { r[e] = fmaxf(r[e], r[f]); c[f] = -1; }
                atomicMax((unsigned int*)&agg3[(size_t)c[e] * 128 + j], __float_as_uint(r[e]));
            }
        }
    }
}

// -------------------- f3 = celu(agg3(128) @ W3g(128x256) + b) ---------------
__global__ void k_f3(const float* __restrict__ agg3, const float* __restrict__ W,
                     const float* __restrict__ b, float* __restrict__ f3, int G) {
    int idx = blockIdx.x * blockDim.x + threadIdx.x;
    if (idx >= G * 256) return;
    int g = idx >> 8, j = idx & 255;
    const float* a = agg3 + g * 128;
    float acc = __ldg(b + j);
#pragma unroll 8
    for (int k = 0; k < 128; k++) acc = fmaf(__ldg(a + k), __ldg(W + k * 256 + j), acc);
    f3[idx] = celu1(acc);
}

// ------- head: out = f3 @ Wlin + blin; mu/sigma/z -> write all outputs -------
__global__ void k_head(const float* __restrict__ f3, const float* __restrict__ W,
                       const float* __restrict__ b, const float* __restrict__ eps,
                       float* __restrict__ out, int G) {
    __shared__ float row[256];
    int g = blockIdx.x;
    int j = threadIdx.x;  // 128
    for (int t = j; t < 256; t += 128) row[t] = f3[g * 256 + t];
    __syncthreads();
    float mu = __ldg(b + j), s = __ldg(b + j + 128);
#pragma unroll 4
    for (int k = 0; k < 256; k++) {
        float x = row[k];
        mu = fmaf(x, __ldg(W + k * 256 + j), mu);
        s = fmaf(x, __ldg(W + k * 256 + j + 128), s);
    }
    float sig = fmaxf(s, 0.0f) + log1pf(expf(-fabsf(s)));
    float z = fmaf(sig, eps[g * 128 + j], mu);
    out[(size_t)G * 128 + g * 128 + j] = mu;
    out[(size_t)G * 256 + g * 128 + j] = sig;
    if (j < 64) out[g * 64 + j] = z;
    else out[(size_t)G * 64 + g * 64 + (j - 64)] = z;
}

// ---------------------------------------------------------------------------
extern "C" void kernel_launch(void* const* d_in, const int* in_sizes, int n_in,
                              void* d_out, int out_size) {
    const float* rgb = (const float*)d_in[0];
    const float* pos = (const float*)d_in[1];
    const float* W1l = (const float*)d_in[3];
    const float* b1l = (const float*)d_in[4];
    const float* W1g = (const float*)d_in[5];
    const float* b1g = (const float*)d_in[6];
    const float* W2l = (const float*)d_in[7];
    const float* b2l = (const float*)d_in[8];
    const float* W2g = (const float*)d_in[9];
    const float* b2g = (const float*)d_in[10];
    const float* W3l = (const float*)d_in[11];
    const float* b3l = (const float*)d_in[12];
    const float* W3g = (const float*)d_in[13];
    const float* b3g = (const float*)d_in[14];
    const float* Wlin = (const float*)d_in[15];
    const float* blin = (const float*)d_in[16];
    const float* eps = (const float*)d_in[17];
    const int* cl1 = (const int*)d_in[19];
    const int* cl2 = (const int*)d_in[20];
    const int* bt2 = (const int*)d_in[21];

    int N = in_sizes[0];
    int G = in_sizes[2] / 3;
    int M1 = in_sizes[20];
    int M2 = in_sizes[21];

    float* A = nullptr;
    cudaGetSymbolAddress((void**)&A, g_arena);
    size_t o = 0;
    float* ps1 = A + o;  o += 3ull * M1;
    float* cnt1 = A + o; o += (size_t)M1;
    float* agg1 = A + o; o += 16ull * M1;
    float* ps2 = A + o;  o += 3ull * M2;
    float* cnt2 = A + o; o += (size_t)M2;
    float* agg2 = A + o; o += 64ull * M2;
    float* agg3 = A + o; o += 128ull * G;
    float* Wp1g = A + o; o += 512;
    float* Wp2l = A + o; o += 2304;
    float* Wp2g = A + o; o += 8192;
    float* Wp3l = A + o; o += 16896;

    float* out = (float*)d_out;
    float* f3 = out + (size_t)G * 384;

    k_prep<<<(512 + 2304 + 8192 + 16896 + 255) / 256, 256>>>(W1g, W2l, W2g, W3l,
                                                             Wp1g, Wp2l, Wp2g, Wp3l);
    cudaMemsetAsync(ps1, 0, 20ull * M1 * sizeof(float), 0);
    cudaMemsetAsync(ps2, 0, 68ull * M2 * sizeof(float), 0);
    cudaMemsetAsync(agg3, 0, 128ull * G * sizeof(float), 0);

    k_scatter_mean<<<(N + 255) / 256, 256>>>(pos, cl1, ps1, cnt1, N);
    k_div3<<<(M1 + 255) / 256, 256>>>(ps1, cnt1, M1);
    k_edge1<<<(N + 255) / 256, 256>>>(rgb, pos, ps1, cl1, W1l, b1l, agg1, N);

    k_scatter_mean<<<(M1 + 255) / 256, 256>>>(ps1, cl2, ps2, cnt2, M1);
    k_div3<<<(M2 + 255) / 256, 256>>>(ps2, cnt2, M2);

    k_edge2f<<<1184, 256>>>(agg1, ps1, ps2, cl2, Wp1g, b1g, Wp2l, b2l, agg2, M1);

    cudaFuncSetAttribute(k_edge3f, cudaFuncAttributeMaxDynamicSharedMemorySize,
                         SM3 * sizeof(float));
    k_edge3f<<<296, 256, SM3 * sizeof(float)>>>(agg2, ps2, bt2, Wp2g, b2g, Wp3l, b3l,
                                                agg3, M2);

    k_f3<<<(G * 256 + 255) / 256, 256>>>(agg3, W3g, b3g, f3, G);
    k_head<<<G, 128>>>(f3, Wlin, blin, eps, out, G);
}